// round 15
// baseline (speedup 1.0000x reference)
#include <cuda_runtime.h>
#include <math.h>

#define T_SEQ 256
#define E_DIM 1024
#define H_DIM 2048
#define LATD  512
#define CLSD  512
#define MIXD  384
#define VJD   64
#define ALPH  32

#define NBLK  148
#define NTHR  1024
#define NWARPS (NBLK * (NTHR/32))
#define GRID_THREADS (NBLK * NTHR)
#define HBLK  74            // blocks per decoder chain
#define SMEM_JE 12          // encoder j-slots cached in smem (x16KB = 192KB)
#define SWTS_U4 (SMEM_JE * 1024)

// output layout (float32)
#define OFF_LATF 0
#define OFF_LATR 640
#define OFF_RECF 1280
#define OFF_RECR (1280 + T_SEQ*E_DIM)
#define OFF_EMBF (1280 + 2*T_SEQ*E_DIM)
#define OFF_EMBR (1280 + 3*T_SEQ*E_DIM)

// ---------------- persistent scratch --------------------------------------
__device__ __align__(16) float g_h[2][2][H_DIM];   // encoder hidden ping-pong
__device__ __align__(16) float g_c[2][H_DIM];      // encoder cell (SM-local)
__device__ __align__(16) float g_common[CLSD];
__device__ __align__(16) float g_h0[2][E_DIM];     // decoder initial state
__device__ __align__(16) float g_dh[2][2][E_DIM];  // decoder hidden ping-pong
__device__ __align__(16) float g_dp0[2][E_DIM];    // decoder step-0 input
__device__ __align__(16) float g_dc[2][E_DIM];     // decoder cell (SM-local)

// int16 quantized weights (per-row scale), built in phase A each launch.
// PERMUTED: uint4 #u of a row holds two far-apart float4-groups so compute
// reads contiguous LDS for activations.
__device__ uint4 q_eWhh[4 * H_DIM * (H_DIM/8)];    // 32 MB
__device__ uint4 q_dWf[4 * E_DIM * (E_DIM/8)];     // Wih+Whh summed, 8 MB
__device__ uint4 q_dWr[4 * E_DIM * (E_DIM/8)];     // 8 MB
__device__ float s_eW[4 * H_DIM];
__device__ float s_dWf[4 * E_DIM];
__device__ float s_dWr[4 * E_DIM];

__device__ float g_wx[ALPH * 4 * H_DIM];           // WX_sym + enc bias folded in
__device__ float g_bdf[4 * E_DIM];
__device__ float g_bdr[4 * E_DIM];

// barriers: global counter + per-decoder-chain counters (fan-in 74)
__device__ __align__(128) unsigned int g_ctr[32];
__device__ __align__(128) unsigned int g_ctrF[32];
__device__ __align__(128) unsigned int g_ctrR[32];

__global__ void init_kernel() { g_ctr[0] = 0u; g_ctrF[0] = 0u; g_ctrR[0] = 0u; }

// fast transcendentals (error ~1e-7, negligible vs int16 quant noise)
__device__ __forceinline__ float sig_f(float x)  { return __fdividef(1.0f, 1.0f + __expf(-x)); }
__device__ __forceinline__ float tanh_f(float x) { return __fdividef(2.0f, 1.0f + __expf(-2.0f * x)) - 1.0f; }

// ---- grid barrier: red.release arrive + tight acquire poll -----------------
__device__ __forceinline__ void bar_sync(unsigned int* ctr, unsigned target) {
    asm volatile("red.release.gpu.global.add.u32 [%0], %1;"
                 :: "l"(ctr), "r"(1u) : "memory");
    unsigned v;
    do {
        asm volatile("ld.acquire.gpu.global.u32 %0, [%1];"
                     : "=r"(v) : "l"(ctr) : "memory");
    } while (v < target);
}

__device__ __forceinline__ void grid_sync_fast(unsigned int& round, int tid) {
    __syncthreads();
    round++;
    if (tid == 0) bar_sync(&g_ctr[0], round * (unsigned)NBLK);
    __syncthreads();
}

__device__ __forceinline__ void grid_sync_strong(unsigned int& round, int tid) {
    __threadfence();
    grid_sync_fast(round, tid);
}

__device__ __forceinline__ float warp_sum(float v) {
    #pragma unroll
    for (int off = 16; off; off >>= 1) v += __shfl_xor_sync(0xFFFFFFFFu, v, off);
    return v;
}
__device__ __forceinline__ float warp_max(float v) {
    #pragma unroll
    for (int off = 16; off; off >>= 1) v = fmaxf(v, __shfl_xor_sync(0xFFFFFFFFu, v, off));
    return v;
}
__device__ __forceinline__ float dot4(float4 w, float4 a) {
    return w.x*a.x + w.y*a.y + w.z*a.z + w.w*a.w;
}

// ---- packed f32x2 int16 dot machinery --------------------------------------
#define QMAGIC   0x4B000000u
#define NEGMAG2  0xCB008000CB008000ULL   // packed (-8421376.0f, -8421376.0f)

#define FMA2(d, a, b, c) asm("fma.rn.f32x2 %0, %1, %2, %3;" : "=l"(d) : "l"(a), "l"(b), "l"(c))

__device__ __forceinline__ unsigned long long unpw2(unsigned u) {
    unsigned lo = __byte_perm(u, QMAGIC, 0x7610);
    unsigned hi = __byte_perm(u, QMAGIC, 0x7632);
    unsigned long long p, e;
    asm("mov.b64 %0, {%1, %2};" : "=l"(p) : "r"(lo), "r"(hi));
    const unsigned long long nm = NEGMAG2;
    asm("add.rn.f32x2 %0, %1, %2;" : "=l"(e) : "l"(p), "l"(nm));
    return e;
}
__device__ __forceinline__ float hsum2(unsigned long long v) {
    return __uint_as_float((unsigned)v) + __uint_as_float((unsigned)(v >> 32));
}

__device__ __forceinline__ uint2 quant4(float4 v, float inv) {
    int q0 = __float2int_rn(v.x * inv) + 32768;
    int q1 = __float2int_rn(v.y * inv) + 32768;
    int q2 = __float2int_rn(v.z * inv) + 32768;
    int q3 = __float2int_rn(v.w * inv) + 32768;
    uint2 r;
    r.x = (unsigned)(q0 & 0xFFFF) | ((unsigned)(q1 & 0xFFFF) << 16);
    r.y = (unsigned)(q2 & 0xFFFF) | ((unsigned)(q3 & 0xFFFF) << 16);
    return r;
}

// encoder dual-chain dot over my k-half; qb layout: gate stride gs (uint4)
__device__ __forceinline__ void enc_dot(const uint4* __restrict__ qb, size_t gs,
                                        const ulonglong2* __restrict__ hfp,
                                        const ulonglong2* __restrict__ hrp,
                                        int kbase, int lane,
                                        unsigned long long* af, unsigned long long* ar) {
    #pragma unroll
    for (int i = 0; i < 4; ++i) {
        const int gi = lane + 32 * i;
        ulonglong2 fa = hfp[kbase + gi];
        ulonglong2 fb = hfp[kbase + 128 + gi];
        ulonglong2 ra = hrp[kbase + gi];
        ulonglong2 rb = hrp[kbase + 128 + gi];
        #pragma unroll
        for (int gx = 0; gx < 4; ++gx) {
            uint4 w = qb[(size_t)gx * gs + gi];
            unsigned long long e0 = unpw2(w.x);
            unsigned long long e1 = unpw2(w.y);
            unsigned long long e2 = unpw2(w.z);
            unsigned long long e3 = unpw2(w.w);
            FMA2(af[gx], e0, fa.x, af[gx]);
            FMA2(af[gx], e1, fa.y, af[gx]);
            FMA2(af[gx], e2, fb.x, af[gx]);
            FMA2(af[gx], e3, fb.y, af[gx]);
            FMA2(ar[gx], e0, ra.x, ar[gx]);
            FMA2(ar[gx], e1, ra.y, ar[gx]);
            FMA2(ar[gx], e2, rb.x, ar[gx]);
            FMA2(ar[gx], e3, rb.y, ar[gx]);
        }
    }
}

__global__ __launch_bounds__(NTHR, 1)
void net_kernel(const int* __restrict__ x, const int* __restrict__ Vg, const int* __restrict__ Jg,
                const float* __restrict__ emb, const float* __restrict__ emb_Vg, const float* __restrict__ emb_Jg,
                const float* __restrict__ enc_Wih, const float* __restrict__ enc_Whh,
                const float* __restrict__ enc_bih, const float* __restrict__ enc_bhh,
                const float* __restrict__ cls_W, const float* __restrict__ cls_b,
                const float* __restrict__ latf_W, const float* __restrict__ latf_b,
                const float* __restrict__ latr_W, const float* __restrict__ latr_b,
                const float* __restrict__ mix_W, const float* __restrict__ mix_b,
                const float* __restrict__ recf_Wih, const float* __restrict__ recf_Whh,
                const float* __restrict__ recf_bih, const float* __restrict__ recf_bhh,
                const float* __restrict__ recr_Wih, const float* __restrict__ recr_Whh,
                const float* __restrict__ recr_bih, const float* __restrict__ recr_bhh,
                float* __restrict__ out)
{
    extern __shared__ __align__(16) uint4 swts[];  // 192 KB weight cache
    __shared__ __align__(16) float4 sbuf4[1024];   // 16 KB staging
    __shared__ float sgate[128];                   // split-k partial exchange
    __shared__ int sx[T_SEQ];
    unsigned int round = 0;

    const int tid  = threadIdx.x;
    const int bx   = blockIdx.x;
    const int gtid = bx * NTHR + tid;
    const int lane = tid & 31;
    const int wid  = gtid >> 5;           // global warp id (one-shot phases)
    const int wl   = tid >> 5;            // local warp id (0..31)
    const int wlp  = wl & 15;             // j-slot
    const int kh   = wl >> 4;             // k-half

    // =========== Phase A: quantize (PERMUTED) + WX table + gather + init ======
    for (int row = wid; row < 4 * H_DIM; row += NWARPS) {
        const float4* src = (const float4*)(enc_Whh + (size_t)row * H_DIM);
        float m = 0.f;
        #pragma unroll 4
        for (int i = 0; i < 16; ++i) {
            float4 v = src[lane + 32 * i];
            m = fmaxf(m, fmaxf(fmaxf(fabsf(v.x), fabsf(v.y)), fmaxf(fabsf(v.z), fabsf(v.w))));
        }
        m = warp_max(m);
        float inv = (m > 0.f) ? 32767.0f / m : 0.f;
        uint2* dst2 = (uint2*)(q_eWhh + (size_t)row * (H_DIM/8));
        #pragma unroll 4
        for (int i = 0; i < 16; ++i) {
            int k = lane + 32 * i;              // source float4-group, [0,512)
            int h = k >> 8, r = k & 255;
            int q = r >> 7, pos = r & 127;
            dst2[(h * 128 + pos) * 2 + q] = quant4(src[k], inv);
        }
        if (lane == 0) s_eW[row] = (m > 0.f) ? m / 32767.0f : 0.f;
    }
    for (int r = wid; r < 2 * 4 * E_DIM; r += NWARPS) {
        const int d  = r >> 12;
        const int rr = r & 4095;
        const float4* sa = (const float4*)((d ? recr_Wih : recf_Wih) + (size_t)rr * E_DIM);
        const float4* sb = (const float4*)((d ? recr_Whh : recf_Whh) + (size_t)rr * E_DIM);
        float4 w[8];
        float m = 0.f;
        #pragma unroll
        for (int i = 0; i < 8; ++i) {
            float4 a = sa[lane + 32 * i], b = sb[lane + 32 * i];
            w[i] = make_float4(a.x + b.x, a.y + b.y, a.z + b.z, a.w + b.w);
            m = fmaxf(m, fmaxf(fmaxf(fabsf(w[i].x), fabsf(w[i].y)), fmaxf(fabsf(w[i].z), fabsf(w[i].w))));
        }
        m = warp_max(m);
        float inv = (m > 0.f) ? 32767.0f / m : 0.f;
        uint2* dst2 = (uint2*)((d ? q_dWr : q_dWf) + (size_t)rr * (E_DIM/8));
        #pragma unroll
        for (int i = 0; i < 8; ++i) {
            int k = lane + 32 * i;              // [0,256)
            int h = k >> 7, rk = k & 127;
            int q = rk >> 6, pos = rk & 63;
            dst2[(h * 64 + pos) * 2 + q] = quant4(w[i], inv);
        }
        if (lane == 0) (d ? s_dWr : s_dWf)[rr] = (m > 0.f) ? m / 32767.0f : 0.f;
    }
    // WX table with encoder bias folded in
    for (int row = wid; row < 4 * H_DIM; row += NWARPS) {
        const float4* wr = (const float4*)(enc_Wih + (size_t)row * E_DIM);
        float4 w[8];
        #pragma unroll
        for (int i = 0; i < 8; ++i) w[i] = wr[lane + i * 32];
        float bb = enc_bih[row] + enc_bhh[row];
        for (int sym = 0; sym < ALPH; ++sym) {
            const float4* ev = (const float4*)(emb + (size_t)sym * E_DIM);
            float acc = 0.f;
            #pragma unroll
            for (int i = 0; i < 8; ++i) acc += dot4(w[i], ev[lane + i * 32]);
            acc = warp_sum(acc);
            if (lane == 0) g_wx[sym * 4 * H_DIM + row] = acc + bb;
        }
    }
    for (int i = gtid; i < 4 * E_DIM; i += GRID_THREADS) {
        g_bdf[i] = recf_bih[i] + recf_bhh[i];
        g_bdr[i] = recr_bih[i] + recr_bhh[i];
    }
    for (int idx = gtid; idx < T_SEQ * E_DIM; idx += GRID_THREADS) {
        int t = idx >> 10, e = idx & 1023;
        float v = emb[x[t] * E_DIM + e];
        out[OFF_EMBF + idx] = v;
        out[OFF_EMBR + (T_SEQ - 1 - t) * E_DIM + e] = v;
    }
    for (int e = gtid; e < E_DIM; e += GRID_THREADS) {
        float e0 = emb[e];
        float e1 = emb[E_DIM + e];
        out[OFF_RECF + e] = e1;
        out[OFF_RECF + 255 * E_DIM + e] = e0;
        out[OFF_RECR + e] = e0;
        out[OFF_RECR + 255 * E_DIM + e] = e1;
    }
    {
        float* hflat = &g_h[0][0][0];
        float* cflat = &g_c[0][0];
        for (int j = gtid; j < 2 * H_DIM; j += GRID_THREADS) { hflat[j] = 0.f; cflat[j] = 0.f; }
    }
    for (int t = tid; t < T_SEQ; t += NTHR) sx[t] = x[t];
    grid_sync_strong(round, tid);

    // =========== Encoder: 256 steps, smem weight cache for 12/16 j-slots ======
    {
        const size_t gstride4 = (size_t)H_DIM * (H_DIM/8); // gate stride in uint4
        // load 12 slots x 16 KB into smem (layout: slot*1024 + gate*256 + r)
        for (int idx = tid; idx < SWTS_U4; idx += NTHR) {
            int slot = idx >> 10;
            int rem  = idx & 1023;
            int gate = rem >> 8;
            int r    = rem & 255;
            int jj   = slot * NBLK + bx;
            swts[idx] = q_eWhh[(size_t)gate * gstride4 + (size_t)jj * 256 + r];
        }
        __syncthreads();

        float4* shf4 = sbuf4;
        float4* shr4 = sbuf4 + 512;
        const ulonglong2* hfp = (const ulonglong2*)shf4;
        const ulonglong2* hrp = (const ulonglong2*)shr4;
        const int j = wlp * NBLK + bx;
        const bool jv = (j < H_DIM);
        const bool use_s = (wlp < SMEM_JE);
        const int kbase = kh * 256;
        const uint4* qs = swts + wlp * 1024 + kh * 128;                  // gate stride 256
        const uint4* qg = q_eWhh + (size_t)j * (H_DIM/8) + kh * 128;     // gate stride gstride4

        float sc0 = 0.f, sc1 = 0.f, sc2 = 0.f, sc3 = 0.f;
        if (jv) {
            sc0 = s_eW[j];            sc1 = s_eW[H_DIM + j];
            sc2 = s_eW[2*H_DIM + j];  sc3 = s_eW[3*H_DIM + j];
        }

        for (int t = 0; t < T_SEQ; ++t) {
            const int p = t & 1;
            {   // stage both chains' h
                const int dst = tid >> 9;
                const int off = tid & 511;
                float4 v = __ldcg(((const float4*)g_h[p][dst]) + off);
                (dst ? shr4 : shf4)[off] = v;
            }
            __syncthreads();

            float sf0 = 0.f, sf1 = 0.f, sf2 = 0.f, sf3 = 0.f;
            float sr0 = 0.f, sr1 = 0.f, sr2 = 0.f, sr3 = 0.f;
            if (jv) {
                unsigned long long af[4] = {0ull,0ull,0ull,0ull};
                unsigned long long ar[4] = {0ull,0ull,0ull,0ull};
                if (use_s) enc_dot(qs, 256,      hfp, hrp, kbase, lane, af, ar);
                else       enc_dot(qg, gstride4, hfp, hrp, kbase, lane, af, ar);
                sf0 = warp_sum(hsum2(af[0])); sf1 = warp_sum(hsum2(af[1]));
                sf2 = warp_sum(hsum2(af[2])); sf3 = warp_sum(hsum2(af[3]));
                sr0 = warp_sum(hsum2(ar[0])); sr1 = warp_sum(hsum2(ar[1]));
                sr2 = warp_sum(hsum2(ar[2])); sr3 = warp_sum(hsum2(ar[3]));
                if (kh == 1 && lane == 0) {
                    sgate[wlp*8 + 0] = sf0;  sgate[wlp*8 + 1] = sf1;
                    sgate[wlp*8 + 2] = sf2;  sgate[wlp*8 + 3] = sf3;
                    sgate[wlp*8 + 4] = sr0;  sgate[wlp*8 + 5] = sr1;
                    sgate[wlp*8 + 6] = sr2;  sgate[wlp*8 + 7] = sr3;
                }
            }
            __syncthreads();

            if (jv && kh == 0) {
                const int symf = sx[t];
                const int symr = sx[T_SEQ - 1 - t];
                const float* wxf = g_wx + (size_t)symf * 4 * H_DIM;
                const float* wxr = g_wx + (size_t)symr * 4 * H_DIM;
                float gf0 = (sf0 + sgate[wlp*8 + 0]) * sc0 + wxf[j];
                float gf1 = (sf1 + sgate[wlp*8 + 1]) * sc1 + wxf[H_DIM + j];
                float gf2 = (sf2 + sgate[wlp*8 + 2]) * sc2 + wxf[2*H_DIM + j];
                float gf3 = (sf3 + sgate[wlp*8 + 3]) * sc3 + wxf[3*H_DIM + j];
                float gr0 = (sr0 + sgate[wlp*8 + 4]) * sc0 + wxr[j];
                float gr1 = (sr1 + sgate[wlp*8 + 5]) * sc1 + wxr[H_DIM + j];
                float gr2 = (sr2 + sgate[wlp*8 + 6]) * sc2 + wxr[2*H_DIM + j];
                float gr3 = (sr3 + sgate[wlp*8 + 7]) * sc3 + wxr[3*H_DIM + j];

                const int lg = lane & 3;
                float gv;
                if (lane < 4) gv = (lg == 0) ? gf0 : (lg == 1) ? gf1 : (lg == 2) ? gf2 : gf3;
                else          gv = (lg == 0) ? gr0 : (lg == 1) ? gr1 : (lg == 2) ? gr2 : gr3;
                float act = (lg == 2) ? tanh_f(gv) : sig_f(gv);
                float a_f = __shfl_down_sync(0xFFFFFFFFu, act, 1);
                float a_g = __shfl_down_sync(0xFFFFFFFFu, act, 2);
                float a_o = __shfl_down_sync(0xFFFFFFFFu, act, 3);
                if ((lane & 27) == 0) {
                    const int dd = lane >> 2;
                    float c  = g_c[dd][j];
                    float c2 = a_f * c + act * a_g;
                    g_c[dd][j] = c2;
                    __stcg(&g_h[p ^ 1][dd][j], a_o * tanh_f(c2));
                }
            }
            grid_sync_fast(round, tid);
        }
    }
    // final states at parity 0

    // =========== Phase C1: common, lat_f, lat_r, vg/jg ========================
    {
        float4* shf4 = sbuf4;
        float4* shr4 = sbuf4 + 512;
        {
            const int dst = tid >> 9;
            const int off = tid & 511;
            float4 v = __ldcg(((const float4*)g_h[0][dst]) + off);
            (dst ? shr4 : shf4)[off] = v;
        }
        __syncthreads();
        const float4* hf4 = shf4;
        const float4* hr4 = shr4;
        for (int task = wid; task < 1537; task += NWARPS) {
            if (task < CLSD) {
                const float4* w = (const float4*)(cls_W + (size_t)task * 2 * H_DIM);
                float acc = 0.f;
                for (int k = lane; k < H_DIM / 4; k += 32) {
                    acc += dot4(w[k], hf4[k]);
                    acc += dot4(w[H_DIM/4 + k], hr4[k]);
                }
                acc = warp_sum(acc);
                if (lane == 0) g_common[task] = tanhf(acc + cls_b[task]);
            } else if (task < 1024) {
                const int c = task - 512;
                const float4* w = (const float4*)(latf_W + (size_t)c * H_DIM);
                float acc = 0.f;
                for (int k = lane; k < H_DIM / 4; k += 32) acc += dot4(w[k], hf4[k]);
                acc = warp_sum(acc);
                if (lane == 0) {
                    float v = acc + latf_b[c];
                    g_h0[0][VJD + c] = v;
                    out[OFF_LATF + VJD + c] = v;
                }
            } else if (task < 1536) {
                const int c = task - 1024;
                const float4* w = (const float4*)(latr_W + (size_t)c * H_DIM);
                float acc = 0.f;
                for (int k = lane; k < H_DIM / 4; k += 32) acc += dot4(w[k], hr4[k]);
                acc = warp_sum(acc);
                if (lane == 0) {
                    float v = acc + latr_b[c];
                    g_h0[1][VJD + c] = v;
                    out[OFF_LATR + VJD + c] = v;
                }
            } else {
                const int vgi = Vg[0], jgi = Jg[0];
                for (int k = lane; k < VJD; k += 32) {
                    float v  = emb_Vg[vgi * VJD + k];
                    float jv2 = emb_Jg[jgi * VJD + k];
                    g_h0[0][k] = v;  g_h0[1][k] = v;
                    out[OFF_LATF + k] = v;  out[OFF_LATR + k] = v;
                    g_h0[0][VJD + LATD + k] = jv2;  g_h0[1][VJD + LATD + k] = jv2;
                    out[OFF_LATF + VJD + LATD + k] = jv2;
                    out[OFF_LATR + VJD + LATD + k] = jv2;
                }
            }
        }
    }
    grid_sync_strong(round, tid);

    // =========== Phase C2: mix ================================================
    {
        float* scm = (float*)sbuf4;
        for (int i = tid; i < CLSD; i += NTHR) scm[i] = __ldcg(&g_common[i]);
        __syncthreads();
        const float4* cm4 = (const float4*)scm;
        for (int m = wid; m < MIXD; m += NWARPS) {
            const float4* w = (const float4*)(mix_W + (size_t)m * CLSD);
            float acc = 0.f;
            for (int k = lane; k < CLSD / 4; k += 32) acc += dot4(w[k], cm4[k]);
            acc = warp_sum(acc);
            if (lane == 0) {
                float v = acc + mix_b[m];
                g_h0[0][VJD + LATD + VJD + m] = v;
                g_h0[1][VJD + LATD + VJD + m] = v;
            }
        }
    }
    grid_sync_strong(round, tid);

    // =========== Phase C3: decoder state init =================================
    for (int idx = gtid; idx < 2 * E_DIM; idx += GRID_THREADS) {
        int d = idx >> 10, e = idx & 1023;
        float h0v = __ldcg(&g_h0[d][e]);
        g_dh[0][d][e] = h0v;
        g_dc[d][e]    = h0v;
        g_dp0[d][e]   = emb[(d == 0 ? 0 : 1) * E_DIM + e];
    }
    grid_sync_strong(round, tid);

    // =========== Decoder step 0 (exact fp32; prev != h only here) =============
    {
        float4* sdf4 = sbuf4;
        float4* sdr4 = sbuf4 + 256;
        float4* spf4 = sbuf4 + 512;
        float4* spr4 = sbuf4 + 768;
        if (tid < 256)      sdf4[tid]       = __ldcg(((const float4*)g_dh[0][0]) + tid);
        else if (tid < 512) sdr4[tid - 256] = __ldcg(((const float4*)g_dh[0][1]) + (tid - 256));
        else if (tid < 768) spf4[tid - 512] = __ldcg(((const float4*)g_dp0[0]) + (tid - 512));
        else                spr4[tid - 768] = __ldcg(((const float4*)g_dp0[1]) + (tid - 768));
        __syncthreads();

        const int t0 = wl * NBLK + bx;
        if (t0 < 2 * E_DIM) {
            const int d = t0 >> 10, j = t0 & 1023;
            const float4* wi = (const float4*)(d ? recr_Wih : recf_Wih);
            const float4* wh = (const float4*)(d ? recr_Whh : recf_Whh);
            const float* bsum = d ? g_bdr : g_bdf;
            const float4* ap = d ? spr4 : spf4;
            const float4* ah = d ? sdr4 : sdf4;
            float acc[4] = {0.f, 0.f, 0.f, 0.f};
            #pragma unroll 2
            for (int i = 0; i < 8; ++i) {
                const int k = lane + 32 * i;
                float4 a = ap[k];
                float4 h = ah[k];
                #pragma unroll
                for (int gx = 0; gx < 4; ++gx) {
                    const size_t rb = (size_t)(gx * E_DIM + j) * (E_DIM/4) + k;
                    acc[gx] += dot4(wi[rb], a) + dot4(wh[rb], h);
                }
            }
            #pragma unroll
            for (int gx = 0; gx < 4; ++gx) acc[gx] = warp_sum(acc[gx]);
            if (lane == 0) {
                float g4[4];
                #pragma unroll
                for (int gx = 0; gx < 4; ++gx) g4[gx] = acc[gx] + bsum[gx * E_DIM + j];
                float c  = g_dc[d][j];
                float c2 = sig_f(g4[1]) * c + sig_f(g4[0]) * tanh_f(g4[2]);
                g_dc[d][j] = c2;
                float h2 = sig_f(g4[3]) * tanh_f(c2);
                __stcg(&g_dh[1][d][j], h2);
                out[(d ? OFF_RECR : OFF_RECF) + 254 * E_DIM + j] = h2;
            }
        }
    }
    grid_sync_strong(round, tid);   // all of g_dh[1] visible before chains split

    // =========== Decoder steps 1..253: per-chain barriers, ALL weights smem ===
    {
        float4* sd4 = sbuf4;                               // 256 float4 = my chain's h
        const int chain = (bx >= HBLK) ? 1 : 0;
        const int bc = bx - chain * HBLK;                  // [0,74)
        unsigned int* ctr = chain ? &g_ctrR[0] : &g_ctrF[0];
        const int j = wlp * HBLK + bc;                     // [0,1184)
        const bool jv = (j < E_DIM);
        const int kbase = kh * 128;
        const size_t dstride4 = (size_t)E_DIM * (E_DIM/8);
        const float* sW = chain ? s_dWr : s_dWf;
        const float* bsum = chain ? g_bdr : g_bdf;

        // load ALL 16 slots (128 KB) into smem: slot*512 + gate*128 + r
        {
            const uint4* qsrc = chain ? q_dWr : q_dWf;
            for (int idx = tid; idx < 16 * 512; idx += NTHR) {
                int slot = idx >> 9;
                int rem  = idx & 511;
                int gate = rem >> 7;
                int r    = rem & 127;
                int jj   = slot * HBLK + bc;
                swts[idx] = (jj < E_DIM)
                          ? qsrc[(size_t)gate * dstride4 + (size_t)jj * 128 + r]
                          : make_uint4(0u, 0u, 0u, 0u);
            }
        }
        __syncthreads();
        const uint4* qd = swts + wlp * 512 + kh * 64;      // gate stride 128

        float sc0 = 0.f, sc1 = 0.f, sc2 = 0.f, sc3 = 0.f;
        float bb0 = 0.f, bb1 = 0.f, bb2 = 0.f, bb3 = 0.f;
        if (jv) {
            sc0 = sW[j];            bb0 = bsum[j];
            sc1 = sW[E_DIM + j];    bb1 = bsum[E_DIM + j];
            sc2 = sW[2*E_DIM + j];  bb2 = bsum[2*E_DIM + j];
            sc3 = sW[3*E_DIM + j];  bb3 = bsum[3*E_DIM + j];
        }

        unsigned int dround = 0;
        for (int s = 1; s < T_SEQ - 2; ++s) {
            const int p = s & 1;
            if (tid < 256) sd4[tid] = __ldcg(((const float4*)g_dh[p][chain]) + tid);
            __syncthreads();

            float s0 = 0.f, s1 = 0.f, s2 = 0.f, s3 = 0.f;
            if (jv) {
                const ulonglong2* ap = (const ulonglong2*)sd4;
                unsigned long long acc[4] = {0ull, 0ull, 0ull, 0ull};
                #pragma unroll
                for (int i = 0; i < 2; ++i) {
                    const int gi = lane + 32 * i;
                    ulonglong2 a = ap[kbase + gi];
                    ulonglong2 b = ap[kbase + 64 + gi];
                    #pragma unroll
                    for (int gx = 0; gx < 4; ++gx) {
                        uint4 w = qd[gx * 128 + gi];
                        unsigned long long e0 = unpw2(w.x);
                        unsigned long long e1 = unpw2(w.y);
                        unsigned long long e2 = unpw2(w.z);
                        unsigned long long e3 = unpw2(w.w);
                        FMA2(acc[gx], e0, a.x, acc[gx]);
                        FMA2(acc[gx], e1, a.y, acc[gx]);
                        FMA2(acc[gx], e2, b.x, acc[gx]);
                        FMA2(acc[gx], e3, b.y, acc[gx]);
                    }
                }
                s0 = warp_sum(hsum2(acc[0]));
                s1 = warp_sum(hsum2(acc[1]));
                s2 = warp_sum(hsum2(acc[2]));
                s3 = warp_sum(hsum2(acc[3]));
                if (kh == 1 && lane == 0) {
                    sgate[wlp*4 + 0] = s0;  sgate[wlp*4 + 1] = s1;
                    sgate[wlp*4 + 2] = s2;  sgate[wlp*4 + 3] = s3;
                }
            }
            __syncthreads();

            if (jv && kh == 0) {
                float t0g = (s0 + sgate[wlp*4 + 0]) * sc0 + bb0;
                float t1g = (s1 + sgate[wlp*4 + 1]) * sc1 + bb1;
                float t2g = (s2 + sgate[wlp*4 + 2]) * sc2 + bb2;
                float t3g = (s3 + sgate[wlp*4 + 3]) * sc3 + bb3;

                const int lg = lane & 3;
                float gv = (lg == 0) ? t0g : (lg == 1) ? t1g : (lg == 2) ? t2g : t3g;
                float act = (lg == 2) ? tanh_f(gv) : sig_f(gv);
                float a_f = __shfl_down_sync(0xFFFFFFFFu, act, 1);
                float a_g = __shfl_down_sync(0xFFFFFFFFu, act, 2);
                float a_o = __shfl_down_sync(0xFFFFFFFFu, act, 3);
                if (lane == 0) {
                    float c  = g_dc[chain][j];
                    float c2 = a_f * c + act * a_g;
                    g_dc[chain][j] = c2;
                    float h2 = a_o * tanh_f(c2);
                    __stcg(&g_dh[p ^ 1][chain][j], h2);
                    out[(chain ? OFF_RECR : OFF_RECF) + (254 - s) * E_DIM + j] = h2;
                }
            }
            // per-chain barrier (fan-in 74)
            __syncthreads();
            dround++;
            if (tid == 0) bar_sync(ctr, dround * (unsigned)HBLK);
            __syncthreads();
        }
    }
}

extern "C" void kernel_launch(void* const* d_in, const int* in_sizes, int n_in,
                              void* d_out, int out_size) {
    (void)in_sizes; (void)n_in; (void)out_size;
    static bool attr_set = false;
    if (!attr_set) {
        cudaFuncSetAttribute(net_kernel,
                             cudaFuncAttributeMaxDynamicSharedMemorySize,
                             SWTS_U4 * 16);
        attr_set = true;
    }
    init_kernel<<<1, 1>>>();
    net_kernel<<<NBLK, NTHR, SWTS_U4 * 16>>>(
        (const int*)d_in[0],     // x
        (const int*)d_in[1],     // Vg
        (const int*)d_in[2],     // Jg
        (const float*)d_in[3],   // emb
        (const float*)d_in[4],   // emb_Vg
        (const float*)d_in[5],   // emb_Jg
        (const float*)d_in[6],   // enc_Wih
        (const float*)d_in[7],   // enc_Whh
        (const float*)d_in[8],   // enc_bih
        (const float*)d_in[9],   // enc_bhh
        (const float*)d_in[10],  // cls_W
        (const float*)d_in[11],  // cls_b
        (const float*)d_in[12],  // latf_W
        (const float*)d_in[13],  // latf_b
        (const float*)d_in[14],  // latr_W
        (const float*)d_in[15],  // latr_b
        (const float*)d_in[16],  // mix_W
        (const float*)d_in[17],  // mix_b
        (const float*)d_in[18],  // recf_Wih
        (const float*)d_in[19],  // recf_Whh
        (const float*)d_in[20],  // recf_bih
        (const float*)d_in[21],  // recf_bhh
        (const float*)d_in[22],  // recr_Wih
        (const float*)d_in[23],  // recr_Whh
        (const float*)d_in[24],  // recr_bih
        (const float*)d_in[25],  // recr_bhh
        (float*)d_out);
}

// round 16
// speedup vs baseline: 1.3700x; 1.3700x over previous
#include <cuda_runtime.h>
#include <math.h>

#define T_SEQ 256
#define E_DIM 1024
#define H_DIM 2048
#define LATD  512
#define CLSD  512
#define MIXD  384
#define VJD   64
#define ALPH  32

#define NBLK  148
#define NTHR  1024
#define NWARPS (NBLK * (NTHR/32))
#define GRID_THREADS (NBLK * NTHR)
#define HBLK  74            // blocks per decoder chain

// output layout (float32)
#define OFF_LATF 0
#define OFF_LATR 640
#define OFF_RECF 1280
#define OFF_RECR (1280 + T_SEQ*E_DIM)
#define OFF_EMBF (1280 + 2*T_SEQ*E_DIM)
#define OFF_EMBR (1280 + 3*T_SEQ*E_DIM)

// ---------------- persistent scratch --------------------------------------
__device__ __align__(16) float g_h[2][2][H_DIM];   // encoder hidden ping-pong
__device__ __align__(16) float g_c[2][H_DIM];      // encoder cell (SM-local)
__device__ __align__(16) float g_common[CLSD];
__device__ __align__(16) float g_h0[2][E_DIM];     // decoder initial state
__device__ __align__(16) float g_dh[2][2][E_DIM];  // decoder hidden ping-pong
__device__ __align__(16) float g_dp0[2][E_DIM];    // decoder step-0 input
__device__ __align__(16) float g_dc[2][E_DIM];     // decoder cell (SM-local)

// int16 quantized weights (per-row scale), built in phase A each launch.
// PERMUTED layout: uint4 #u of a row holds groups (half*G/2 + pos) [lo uint2]
// and (half*G/2 + G/4 + pos) [hi uint2] so compute reads contiguous LDS.
__device__ uint4 q_eWhh[4 * H_DIM * (H_DIM/8)];    // 32 MB
__device__ uint4 q_dWf[4 * E_DIM * (E_DIM/8)];     // Wih+Whh summed, 8 MB
__device__ uint4 q_dWr[4 * E_DIM * (E_DIM/8)];     // 8 MB
__device__ float s_eW[4 * H_DIM];
__device__ float s_dWf[4 * E_DIM];
__device__ float s_dWr[4 * E_DIM];

__device__ float g_wx[ALPH * 4 * H_DIM];           // WX_sym + enc bias folded in
__device__ float g_bdf[4 * E_DIM];
__device__ float g_bdr[4 * E_DIM];

// barriers: global counter + per-decoder-chain counters (fan-in 74)
__device__ __align__(128) unsigned int g_ctr[32];
__device__ __align__(128) unsigned int g_ctrF[32];
__device__ __align__(128) unsigned int g_ctrR[32];

__global__ void init_kernel() { g_ctr[0] = 0u; g_ctrF[0] = 0u; g_ctrR[0] = 0u; }

// fast transcendentals (error ~1e-7, negligible vs int16 quant noise)
__device__ __forceinline__ float sig_f(float x)  { return __fdividef(1.0f, 1.0f + __expf(-x)); }
__device__ __forceinline__ float tanh_f(float x) { return __fdividef(2.0f, 1.0f + __expf(-2.0f * x)) - 1.0f; }

// ---- grid barrier: red.release arrive + tight acquire poll -----------------
__device__ __forceinline__ void bar_sync(unsigned int* ctr, unsigned target) {
    asm volatile("red.release.gpu.global.add.u32 [%0], %1;"
                 :: "l"(ctr), "r"(1u) : "memory");
    unsigned v;
    do {
        asm volatile("ld.acquire.gpu.global.u32 %0, [%1];"
                     : "=r"(v) : "l"(ctr) : "memory");
    } while (v < target);
}

__device__ __forceinline__ void grid_sync_fast(unsigned int& round, int tid) {
    __syncthreads();
    round++;
    if (tid == 0) bar_sync(&g_ctr[0], round * (unsigned)NBLK);
    __syncthreads();
}

__device__ __forceinline__ void grid_sync_strong(unsigned int& round, int tid) {
    __threadfence();
    grid_sync_fast(round, tid);
}

__device__ __forceinline__ float warp_sum(float v) {
    #pragma unroll
    for (int off = 16; off; off >>= 1) v += __shfl_xor_sync(0xFFFFFFFFu, v, off);
    return v;
}
__device__ __forceinline__ float warp_max(float v) {
    #pragma unroll
    for (int off = 16; off; off >>= 1) v = fmaxf(v, __shfl_xor_sync(0xFFFFFFFFu, v, off));
    return v;
}
__device__ __forceinline__ float dot4(float4 w, float4 a) {
    return w.x*a.x + w.y*a.y + w.z*a.z + w.w*a.w;
}

// ---- packed f32x2 int16 dot machinery --------------------------------------
#define QMAGIC   0x4B000000u
#define NEGMAG2  0xCB008000CB008000ULL   // packed (-8421376.0f, -8421376.0f)

#define FMA2(d, a, b, c) asm("fma.rn.f32x2 %0, %1, %2, %3;" : "=l"(d) : "l"(a), "l"(b), "l"(c))

__device__ __forceinline__ unsigned long long unpw2(unsigned u) {
    unsigned lo = __byte_perm(u, QMAGIC, 0x7610);
    unsigned hi = __byte_perm(u, QMAGIC, 0x7632);
    unsigned long long p, e;
    asm("mov.b64 %0, {%1, %2};" : "=l"(p) : "r"(lo), "r"(hi));
    const unsigned long long nm = NEGMAG2;
    asm("add.rn.f32x2 %0, %1, %2;" : "=l"(e) : "l"(p), "l"(nm));
    return e;
}
__device__ __forceinline__ float hsum2(unsigned long long v) {
    return __uint_as_float((unsigned)v) + __uint_as_float((unsigned)(v >> 32));
}

__device__ __forceinline__ uint2 quant4(float4 v, float inv) {
    int q0 = __float2int_rn(v.x * inv) + 32768;
    int q1 = __float2int_rn(v.y * inv) + 32768;
    int q2 = __float2int_rn(v.z * inv) + 32768;
    int q3 = __float2int_rn(v.w * inv) + 32768;
    uint2 r;
    r.x = (unsigned)(q0 & 0xFFFF) | ((unsigned)(q1 & 0xFFFF) << 16);
    r.y = (unsigned)(q2 & 0xFFFF) | ((unsigned)(q3 & 0xFFFF) << 16);
    return r;
}

__global__ __launch_bounds__(NTHR, 1)
void net_kernel(const int* __restrict__ x, const int* __restrict__ Vg, const int* __restrict__ Jg,
                const float* __restrict__ emb, const float* __restrict__ emb_Vg, const float* __restrict__ emb_Jg,
                const float* __restrict__ enc_Wih, const float* __restrict__ enc_Whh,
                const float* __restrict__ enc_bih, const float* __restrict__ enc_bhh,
                const float* __restrict__ cls_W, const float* __restrict__ cls_b,
                const float* __restrict__ latf_W, const float* __restrict__ latf_b,
                const float* __restrict__ latr_W, const float* __restrict__ latr_b,
                const float* __restrict__ mix_W, const float* __restrict__ mix_b,
                const float* __restrict__ recf_Wih, const float* __restrict__ recf_Whh,
                const float* __restrict__ recf_bih, const float* __restrict__ recf_bhh,
                const float* __restrict__ recr_Wih, const float* __restrict__ recr_Whh,
                const float* __restrict__ recr_bih, const float* __restrict__ recr_bhh,
                float* __restrict__ out)
{
    __shared__ __align__(16) float4 sbuf4[1024];   // 16 KB staging
    __shared__ float sgate[128];                   // split-k partial exchange
    __shared__ int sx[T_SEQ];
    unsigned int round = 0;

    const int tid  = threadIdx.x;
    const int bx   = blockIdx.x;
    const int gtid = bx * NTHR + tid;
    const int lane = tid & 31;
    const int wid  = gtid >> 5;           // global warp id (one-shot phases)
    const int wl   = tid >> 5;            // local warp id (0..31)
    const int wlp  = wl & 15;             // j-slot
    const int kh   = wl >> 4;             // k-half

    // =========== Phase A: quantize (PERMUTED) + WX table + gather + init ======
    for (int row = wid; row < 4 * H_DIM; row += NWARPS) {
        const float4* src = (const float4*)(enc_Whh + (size_t)row * H_DIM);
        float m = 0.f;
        #pragma unroll 4
        for (int i = 0; i < 16; ++i) {
            float4 v = src[lane + 32 * i];
            m = fmaxf(m, fmaxf(fmaxf(fabsf(v.x), fabsf(v.y)), fmaxf(fabsf(v.z), fabsf(v.w))));
        }
        m = warp_max(m);
        float inv = (m > 0.f) ? 32767.0f / m : 0.f;
        uint2* dst2 = (uint2*)(q_eWhh + (size_t)row * (H_DIM/8));
        #pragma unroll 4
        for (int i = 0; i < 16; ++i) {
            int k = lane + 32 * i;              // source float4-group, [0,512)
            int h = k >> 8, r = k & 255;
            int q = r >> 7, pos = r & 127;
            dst2[(h * 128 + pos) * 2 + q] = quant4(src[k], inv);
        }
        if (lane == 0) s_eW[row] = (m > 0.f) ? m / 32767.0f : 0.f;
    }
    for (int r = wid; r < 2 * 4 * E_DIM; r += NWARPS) {
        const int d  = r >> 12;
        const int rr = r & 4095;
        const float4* sa = (const float4*)((d ? recr_Wih : recf_Wih) + (size_t)rr * E_DIM);
        const float4* sb = (const float4*)((d ? recr_Whh : recf_Whh) + (size_t)rr * E_DIM);
        float4 w[8];
        float m = 0.f;
        #pragma unroll
        for (int i = 0; i < 8; ++i) {
            float4 a = sa[lane + 32 * i], b = sb[lane + 32 * i];
            w[i] = make_float4(a.x + b.x, a.y + b.y, a.z + b.z, a.w + b.w);
            m = fmaxf(m, fmaxf(fmaxf(fabsf(w[i].x), fabsf(w[i].y)), fmaxf(fabsf(w[i].z), fabsf(w[i].w))));
        }
        m = warp_max(m);
        float inv = (m > 0.f) ? 32767.0f / m : 0.f;
        uint2* dst2 = (uint2*)((d ? q_dWr : q_dWf) + (size_t)rr * (E_DIM/8));
        #pragma unroll
        for (int i = 0; i < 8; ++i) {
            int k = lane + 32 * i;              // [0,256)
            int h = k >> 7, rk = k & 127;
            int q = rk >> 6, pos = rk & 63;
            dst2[(h * 64 + pos) * 2 + q] = quant4(w[i], inv);
        }
        if (lane == 0) (d ? s_dWr : s_dWf)[rr] = (m > 0.f) ? m / 32767.0f : 0.f;
    }
    // WX table with encoder bias folded in
    for (int row = wid; row < 4 * H_DIM; row += NWARPS) {
        const float4* wr = (const float4*)(enc_Wih + (size_t)row * E_DIM);
        float4 w[8];
        #pragma unroll
        for (int i = 0; i < 8; ++i) w[i] = wr[lane + i * 32];
        float bb = enc_bih[row] + enc_bhh[row];
        for (int sym = 0; sym < ALPH; ++sym) {
            const float4* ev = (const float4*)(emb + (size_t)sym * E_DIM);
            float acc = 0.f;
            #pragma unroll
            for (int i = 0; i < 8; ++i) acc += dot4(w[i], ev[lane + i * 32]);
            acc = warp_sum(acc);
            if (lane == 0) g_wx[sym * 4 * H_DIM + row] = acc + bb;
        }
    }
    for (int i = gtid; i < 4 * E_DIM; i += GRID_THREADS) {
        g_bdf[i] = recf_bih[i] + recf_bhh[i];
        g_bdr[i] = recr_bih[i] + recr_bhh[i];
    }
    for (int idx = gtid; idx < T_SEQ * E_DIM; idx += GRID_THREADS) {
        int t = idx >> 10, e = idx & 1023;
        float v = emb[x[t] * E_DIM + e];
        out[OFF_EMBF + idx] = v;
        out[OFF_EMBR + (T_SEQ - 1 - t) * E_DIM + e] = v;
    }
    for (int e = gtid; e < E_DIM; e += GRID_THREADS) {
        float e0 = emb[e];
        float e1 = emb[E_DIM + e];
        out[OFF_RECF + e] = e1;
        out[OFF_RECF + 255 * E_DIM + e] = e0;
        out[OFF_RECR + e] = e0;
        out[OFF_RECR + 255 * E_DIM + e] = e1;
    }
    {
        float* hflat = &g_h[0][0][0];
        float* cflat = &g_c[0][0];
        for (int j = gtid; j < 2 * H_DIM; j += GRID_THREADS) { hflat[j] = 0.f; cflat[j] = 0.f; }
    }
    for (int t = tid; t < T_SEQ; t += NTHR) sx[t] = x[t];
    grid_sync_strong(round, tid);

    // =========== Encoder: 256 steps, split-k warp pairs, uint4 weights ========
    {
        float4* shf4 = sbuf4;
        float4* shr4 = sbuf4 + 512;
        const ulonglong2* hfp = (const ulonglong2*)shf4;
        const ulonglong2* hrp = (const ulonglong2*)shr4;
        const int j = wlp * NBLK + bx;
        const bool jv = (j < H_DIM);
        const int kbase = kh * 256;                        // my half in float4-groups
        const uint4* qb4 = q_eWhh + (size_t)j * (H_DIM/8) + kh * 128;
        const size_t gstride4 = (size_t)H_DIM * (H_DIM/8); // gate stride in uint4

        float sc0 = 0.f, sc1 = 0.f, sc2 = 0.f, sc3 = 0.f;
        if (jv) {
            sc0 = s_eW[j];            sc1 = s_eW[H_DIM + j];
            sc2 = s_eW[2*H_DIM + j];  sc3 = s_eW[3*H_DIM + j];
        }

        for (int t = 0; t < T_SEQ; ++t) {
            const int p = t & 1;
            {   // stage both chains' h: 1024 threads x 1 float4 (conflict-free)
                const int dst = tid >> 9;
                const int off = tid & 511;
                float4 v = __ldcg(((const float4*)g_h[p][dst]) + off);
                (dst ? shr4 : shf4)[off] = v;
            }
            __syncthreads();

            float sf0 = 0.f, sf1 = 0.f, sf2 = 0.f, sf3 = 0.f;
            float sr0 = 0.f, sr1 = 0.f, sr2 = 0.f, sr3 = 0.f;
            if (jv) {
                unsigned long long af[4] = {0ull,0ull,0ull,0ull};
                unsigned long long ar[4] = {0ull,0ull,0ull,0ull};
                #pragma unroll
                for (int i = 0; i < 4; ++i) {
                    const int gi = lane + 32 * i;          // [0,128)
                    ulonglong2 fa = hfp[kbase + gi];       // contiguous LDS
                    ulonglong2 fb = hfp[kbase + 128 + gi];
                    ulonglong2 ra = hrp[kbase + gi];
                    ulonglong2 rb = hrp[kbase + 128 + gi];
                    #pragma unroll
                    for (int gx = 0; gx < 4; ++gx) {
                        uint4 w = qb4[(size_t)gx * gstride4 + gi];
                        unsigned long long e0 = unpw2(w.x);
                        unsigned long long e1 = unpw2(w.y);
                        unsigned long long e2 = unpw2(w.z);
                        unsigned long long e3 = unpw2(w.w);
                        FMA2(af[gx], e0, fa.x, af[gx]);
                        FMA2(af[gx], e1, fa.y, af[gx]);
                        FMA2(af[gx], e2, fb.x, af[gx]);
                        FMA2(af[gx], e3, fb.y, af[gx]);
                        FMA2(ar[gx], e0, ra.x, ar[gx]);
                        FMA2(ar[gx], e1, ra.y, ar[gx]);
                        FMA2(ar[gx], e2, rb.x, ar[gx]);
                        FMA2(ar[gx], e3, rb.y, ar[gx]);
                    }
                }
                sf0 = warp_sum(hsum2(af[0])); sf1 = warp_sum(hsum2(af[1]));
                sf2 = warp_sum(hsum2(af[2])); sf3 = warp_sum(hsum2(af[3]));
                sr0 = warp_sum(hsum2(ar[0])); sr1 = warp_sum(hsum2(ar[1]));
                sr2 = warp_sum(hsum2(ar[2])); sr3 = warp_sum(hsum2(ar[3]));
                if (kh == 1 && lane == 0) {
                    sgate[wlp*8 + 0] = sf0;  sgate[wlp*8 + 1] = sf1;
                    sgate[wlp*8 + 2] = sf2;  sgate[wlp*8 + 3] = sf3;
                    sgate[wlp*8 + 4] = sr0;  sgate[wlp*8 + 5] = sr1;
                    sgate[wlp*8 + 6] = sr2;  sgate[wlp*8 + 7] = sr3;
                }
            }
            __syncthreads();

            if (jv && kh == 0) {
                const int symf = sx[t];
                const int symr = sx[T_SEQ - 1 - t];
                const float* wxf = g_wx + (size_t)symf * 4 * H_DIM;
                const float* wxr = g_wx + (size_t)symr * 4 * H_DIM;
                float gf0 = (sf0 + sgate[wlp*8 + 0]) * sc0 + wxf[j];
                float gf1 = (sf1 + sgate[wlp*8 + 1]) * sc1 + wxf[H_DIM + j];
                float gf2 = (sf2 + sgate[wlp*8 + 2]) * sc2 + wxf[2*H_DIM + j];
                float gf3 = (sf3 + sgate[wlp*8 + 3]) * sc3 + wxf[3*H_DIM + j];
                float gr0 = (sr0 + sgate[wlp*8 + 4]) * sc0 + wxr[j];
                float gr1 = (sr1 + sgate[wlp*8 + 5]) * sc1 + wxr[H_DIM + j];
                float gr2 = (sr2 + sgate[wlp*8 + 6]) * sc2 + wxr[2*H_DIM + j];
                float gr3 = (sr3 + sgate[wlp*8 + 7]) * sc3 + wxr[3*H_DIM + j];

                const int lg = lane & 3;
                float gv;
                if (lane < 4) gv = (lg == 0) ? gf0 : (lg == 1) ? gf1 : (lg == 2) ? gf2 : gf3;
                else          gv = (lg == 0) ? gr0 : (lg == 1) ? gr1 : (lg == 2) ? gr2 : gr3;
                float act = (lg == 2) ? tanh_f(gv) : sig_f(gv);
                float a_f = __shfl_down_sync(0xFFFFFFFFu, act, 1);
                float a_g = __shfl_down_sync(0xFFFFFFFFu, act, 2);
                float a_o = __shfl_down_sync(0xFFFFFFFFu, act, 3);
                if ((lane & 27) == 0) {
                    const int dd = lane >> 2;
                    float c  = g_c[dd][j];
                    float c2 = a_f * c + act * a_g;
                    g_c[dd][j] = c2;
                    __stcg(&g_h[p ^ 1][dd][j], a_o * tanh_f(c2));
                }
            }
            grid_sync_fast(round, tid);
        }
    }
    // final states at parity 0

    // =========== Phase C1: common, lat_f, lat_r, vg/jg ========================
    {
        float4* shf4 = sbuf4;
        float4* shr4 = sbuf4 + 512;
        {
            const int dst = tid >> 9;
            const int off = tid & 511;
            float4 v = __ldcg(((const float4*)g_h[0][dst]) + off);
            (dst ? shr4 : shf4)[off] = v;
        }
        __syncthreads();
        const float4* hf4 = shf4;
        const float4* hr4 = shr4;
        for (int task = wid; task < 1537; task += NWARPS) {
            if (task < CLSD) {
                const float4* w = (const float4*)(cls_W + (size_t)task * 2 * H_DIM);
                float acc = 0.f;
                for (int k = lane; k < H_DIM / 4; k += 32) {
                    acc += dot4(w[k], hf4[k]);
                    acc += dot4(w[H_DIM/4 + k], hr4[k]);
                }
                acc = warp_sum(acc);
                if (lane == 0) g_common[task] = tanhf(acc + cls_b[task]);
            } else if (task < 1024) {
                const int c = task - 512;
                const float4* w = (const float4*)(latf_W + (size_t)c * H_DIM);
                float acc = 0.f;
                for (int k = lane; k < H_DIM / 4; k += 32) acc += dot4(w[k], hf4[k]);
                acc = warp_sum(acc);
                if (lane == 0) {
                    float v = acc + latf_b[c];
                    g_h0[0][VJD + c] = v;
                    out[OFF_LATF + VJD + c] = v;
                }
            } else if (task < 1536) {
                const int c = task - 1024;
                const float4* w = (const float4*)(latr_W + (size_t)c * H_DIM);
                float acc = 0.f;
                for (int k = lane; k < H_DIM / 4; k += 32) acc += dot4(w[k], hr4[k]);
                acc = warp_sum(acc);
                if (lane == 0) {
                    float v = acc + latr_b[c];
                    g_h0[1][VJD + c] = v;
                    out[OFF_LATR + VJD + c] = v;
                }
            } else {
                const int vgi = Vg[0], jgi = Jg[0];
                for (int k = lane; k < VJD; k += 32) {
                    float v  = emb_Vg[vgi * VJD + k];
                    float jv2 = emb_Jg[jgi * VJD + k];
                    g_h0[0][k] = v;  g_h0[1][k] = v;
                    out[OFF_LATF + k] = v;  out[OFF_LATR + k] = v;
                    g_h0[0][VJD + LATD + k] = jv2;  g_h0[1][VJD + LATD + k] = jv2;
                    out[OFF_LATF + VJD + LATD + k] = jv2;
                    out[OFF_LATR + VJD + LATD + k] = jv2;
                }
            }
        }
    }
    grid_sync_strong(round, tid);

    // =========== Phase C2: mix ================================================
    {
        float* scm = (float*)sbuf4;
        for (int i = tid; i < CLSD; i += NTHR) scm[i] = __ldcg(&g_common[i]);
        __syncthreads();
        const float4* cm4 = (const float4*)scm;
        for (int m = wid; m < MIXD; m += NWARPS) {
            const float4* w = (const float4*)(mix_W + (size_t)m * CLSD);
            float acc = 0.f;
            for (int k = lane; k < CLSD / 4; k += 32) acc += dot4(w[k], cm4[k]);
            acc = warp_sum(acc);
            if (lane == 0) {
                float v = acc + mix_b[m];
                g_h0[0][VJD + LATD + VJD + m] = v;
                g_h0[1][VJD + LATD + VJD + m] = v;
            }
        }
    }
    grid_sync_strong(round, tid);

    // =========== Phase C3: decoder state init =================================
    for (int idx = gtid; idx < 2 * E_DIM; idx += GRID_THREADS) {
        int d = idx >> 10, e = idx & 1023;
        float h0v = __ldcg(&g_h0[d][e]);
        g_dh[0][d][e] = h0v;
        g_dc[d][e]    = h0v;
        g_dp0[d][e]   = emb[(d == 0 ? 0 : 1) * E_DIM + e];
    }
    grid_sync_strong(round, tid);

    // =========== Decoder step 0 (exact fp32; prev != h only here) =============
    {
        float4* sdf4 = sbuf4;
        float4* sdr4 = sbuf4 + 256;
        float4* spf4 = sbuf4 + 512;
        float4* spr4 = sbuf4 + 768;
        if (tid < 256)      sdf4[tid]       = __ldcg(((const float4*)g_dh[0][0]) + tid);
        else if (tid < 512) sdr4[tid - 256] = __ldcg(((const float4*)g_dh[0][1]) + (tid - 256));
        else if (tid < 768) spf4[tid - 512] = __ldcg(((const float4*)g_dp0[0]) + (tid - 512));
        else                spr4[tid - 768] = __ldcg(((const float4*)g_dp0[1]) + (tid - 768));
        __syncthreads();

        const int t0 = wl * NBLK + bx;
        if (t0 < 2 * E_DIM) {
            const int d = t0 >> 10, j = t0 & 1023;
            const float4* wi = (const float4*)(d ? recr_Wih : recf_Wih);
            const float4* wh = (const float4*)(d ? recr_Whh : recf_Whh);
            const float* bsum = d ? g_bdr : g_bdf;
            const float4* ap = d ? spr4 : spf4;
            const float4* ah = d ? sdr4 : sdf4;
            float acc[4] = {0.f, 0.f, 0.f, 0.f};
            #pragma unroll 2
            for (int i = 0; i < 8; ++i) {
                const int k = lane + 32 * i;
                float4 a = ap[k];
                float4 h = ah[k];
                #pragma unroll
                for (int gx = 0; gx < 4; ++gx) {
                    const size_t rb = (size_t)(gx * E_DIM + j) * (E_DIM/4) + k;
                    acc[gx] += dot4(wi[rb], a) + dot4(wh[rb], h);
                }
            }
            #pragma unroll
            for (int gx = 0; gx < 4; ++gx) acc[gx] = warp_sum(acc[gx]);
            if (lane == 0) {
                float g4[4];
                #pragma unroll
                for (int gx = 0; gx < 4; ++gx) g4[gx] = acc[gx] + bsum[gx * E_DIM + j];
                float c  = g_dc[d][j];
                float c2 = sig_f(g4[1]) * c + sig_f(g4[0]) * tanh_f(g4[2]);
                g_dc[d][j] = c2;
                float h2 = sig_f(g4[3]) * tanh_f(c2);
                __stcg(&g_dh[1][d][j], h2);
                out[(d ? OFF_RECR : OFF_RECF) + 254 * E_DIM + j] = h2;
            }
        }
    }
    grid_sync_strong(round, tid);   // all of g_dh[1] visible before chains split

    // =========== Decoder steps 1..253: per-chain barriers, uint4 weights ======
    {
        float4* sd4 = sbuf4;                               // 256 float4 = my chain's h
        const int chain = (bx >= HBLK) ? 1 : 0;
        const int bc = bx - chain * HBLK;                  // [0,74)
        unsigned int* ctr = chain ? &g_ctrR[0] : &g_ctrF[0];
        const int j = wlp * HBLK + bc;                     // [0,1184)
        const bool jv = (j < E_DIM);
        const int kbase = kh * 128;                        // half in float4-groups
        const uint4* qd4 = (jv ? (chain ? q_dWr : q_dWf) : q_dWf)
                         + (size_t)j * (E_DIM/8) + kh * 64;
        const size_t dstride4 = (size_t)E_DIM * (E_DIM/8);
        const float* sW = chain ? s_dWr : s_dWf;
        const float* bsum = chain ? g_bdr : g_bdf;

        float sc0 = 0.f, sc1 = 0.f, sc2 = 0.f, sc3 = 0.f;
        float bb0 = 0.f, bb1 = 0.f, bb2 = 0.f, bb3 = 0.f;
        if (jv) {
            sc0 = sW[j];            bb0 = bsum[j];
            sc1 = sW[E_DIM + j];    bb1 = bsum[E_DIM + j];
            sc2 = sW[2*E_DIM + j];  bb2 = bsum[2*E_DIM + j];
            sc3 = sW[3*E_DIM + j];  bb3 = bsum[3*E_DIM + j];
        }

        unsigned int dround = 0;
        for (int s = 1; s < T_SEQ - 2; ++s) {
            const int p = s & 1;
            if (tid < 256) sd4[tid] = __ldcg(((const float4*)g_dh[p][chain]) + tid);
            __syncthreads();

            float s0 = 0.f, s1 = 0.f, s2 = 0.f, s3 = 0.f;
            if (jv) {
                const ulonglong2* ap = (const ulonglong2*)sd4;
                unsigned long long acc[4] = {0ull, 0ull, 0ull, 0ull};
                #pragma unroll
                for (int i = 0; i < 2; ++i) {
                    const int gi = lane + 32 * i;          // [0,64)
                    ulonglong2 a = ap[kbase + gi];
                    ulonglong2 b = ap[kbase + 64 + gi];
                    #pragma unroll
                    for (int gx = 0; gx < 4; ++gx) {
                        uint4 w = qd4[(size_t)gx * dstride4 + gi];
                        unsigned long long e0 = unpw2(w.x);
                        unsigned long long e1 = unpw2(w.y);
                        unsigned long long e2 = unpw2(w.z);
                        unsigned long long e3 = unpw2(w.w);
                        FMA2(acc[gx], e0, a.x, acc[gx]);
                        FMA2(acc[gx], e1, a.y, acc[gx]);
                        FMA2(acc[gx], e2, b.x, acc[gx]);
                        FMA2(acc[gx], e3, b.y, acc[gx]);
                    }
                }
                s0 = warp_sum(hsum2(acc[0]));
                s1 = warp_sum(hsum2(acc[1]));
                s2 = warp_sum(hsum2(acc[2]));
                s3 = warp_sum(hsum2(acc[3]));
                if (kh == 1 && lane == 0) {
                    sgate[wlp*4 + 0] = s0;  sgate[wlp*4 + 1] = s1;
                    sgate[wlp*4 + 2] = s2;  sgate[wlp*4 + 3] = s3;
                }
            }
            __syncthreads();

            if (jv && kh == 0) {
                float t0g = (s0 + sgate[wlp*4 + 0]) * sc0 + bb0;
                float t1g = (s1 + sgate[wlp*4 + 1]) * sc1 + bb1;
                float t2g = (s2 + sgate[wlp*4 + 2]) * sc2 + bb2;
                float t3g = (s3 + sgate[wlp*4 + 3]) * sc3 + bb3;

                const int lg = lane & 3;
                float gv = (lg == 0) ? t0g : (lg == 1) ? t1g : (lg == 2) ? t2g : t3g;
                float act = (lg == 2) ? tanh_f(gv) : sig_f(gv);
                float a_f = __shfl_down_sync(0xFFFFFFFFu, act, 1);
                float a_g = __shfl_down_sync(0xFFFFFFFFu, act, 2);
                float a_o = __shfl_down_sync(0xFFFFFFFFu, act, 3);
                if (lane == 0) {
                    float c  = g_dc[chain][j];
                    float c2 = a_f * c + act * a_g;
                    g_dc[chain][j] = c2;
                    float h2 = a_o * tanh_f(c2);
                    __stcg(&g_dh[p ^ 1][chain][j], h2);
                    out[(chain ? OFF_RECR : OFF_RECF) + (254 - s) * E_DIM + j] = h2;
                }
            }
            // per-chain barrier (fan-in 74)
            __syncthreads();
            dround++;
            if (tid == 0) bar_sync(ctr, dround * (unsigned)HBLK);
            __syncthreads();
        }
    }
}

extern "C" void kernel_launch(void* const* d_in, const int* in_sizes, int n_in,
                              void* d_out, int out_size) {
    (void)in_sizes; (void)n_in; (void)out_size;
    static bool attr_set = false;
    if (!attr_set) {
        // maximize L1D slice: static smem is only ~18 KB, ask for minimal carveout
        cudaFuncSetAttribute(net_kernel,
                             cudaFuncAttributePreferredSharedMemoryCarveout, 8);
        attr_set = true;
    }
    init_kernel<<<1, 1>>>();
    net_kernel<<<NBLK, NTHR>>>(
        (const int*)d_in[0],     // x
        (const int*)d_in[1],     // Vg
        (const int*)d_in[2],     // Jg
        (const float*)d_in[3],   // emb
        (const float*)d_in[4],   // emb_Vg
        (const float*)d_in[5],   // emb_Jg
        (const float*)d_in[6],   // enc_Wih
        (const float*)d_in[7],   // enc_Whh
        (const float*)d_in[8],   // enc_bih
        (const float*)d_in[9],   // enc_bhh
        (const float*)d_in[10],  // cls_W
        (const float*)d_in[11],  // cls_b
        (const float*)d_in[12],  // latf_W
        (const float*)d_in[13],  // latf_b
        (const float*)d_in[14],  // latr_W
        (const float*)d_in[15],  // latr_b
        (const float*)d_in[16],  // mix_W
        (const float*)d_in[17],  // mix_b
        (const float*)d_in[18],  // recf_Wih
        (const float*)d_in[19],  // recf_Whh
        (const float*)d_in[20],  // recf_bih
        (const float*)d_in[21],  // recf_bhh
        (const float*)d_in[22],  // recr_Wih
        (const float*)d_in[23],  // recr_Whh
        (const float*)d_in[24],  // recr_bih
        (const float*)d_in[25],  // recr_bhh
        (float*)d_out);
}